// round 17
// baseline (speedup 1.0000x reference)
#include <cuda_runtime.h>
#include <cuda_bf16.h>
#include <cstdint>

#define BGR   128          // graphs
#define EPG   4096         // edges per graph
#define ETOT  (BGR*EPG)    // 524288 edges
#define FDIM  128
#define NTMAX (BGR*512)    // 65536 max nodes

// ---------------- device scratch ----------------
__device__ __nv_bfloat16 g_Xa_hi[NTMAX*FDIM];   // aggregated input, split bf16
__device__ __nv_bfloat16 g_Xa_lo[NTMAX*FDIM];
__device__ __nv_bfloat16 g_Wt_hi[FDIM*FDIM];    // W transposed [n][k], split bf16
__device__ __nv_bfloat16 g_Wt_lo[FDIM*FDIM];
__device__ float g_bufB[NTMAX*FDIM];   // H  (post-GEMM features)
__device__ float g_bufC[NTMAX*FDIM];   // xnew (next-stage input)
__device__ float g_s0   [NTMAX];
__device__ int   g_src[ETOT];
__device__ int   g_dst[ETOT];
__device__ int   g_csr_src[ETOT];
__device__ float g_csr_w [ETOT];
__device__ int   g_cntA  [NTMAX];
__device__ int   g_offA  [NTMAX];
__device__ int   g_cntB  [NTMAX];
__device__ int   g_offB  [NTMAX];

// =====================================================================
// k_pa1: stage-1 prep + in-block aggregation (MLP=4). 1024 threads;
// extra block (b == BGR) converts W1.  (identical to R15)
// =====================================================================
__global__ __launch_bounds__(1024)
void k_pa1(const int* __restrict__ esrc, const int* __restrict__ edst,
           int* __restrict__ cnt_g, int* __restrict__ off_g,
           int* __restrict__ csr_src_g, float* __restrict__ csr_w_g,
           const float* __restrict__ X,
           __nv_bfloat16* __restrict__ Xa_hi, __nv_bfloat16* __restrict__ Xa_lo,
           const float* __restrict__ W,
           __nv_bfloat16* __restrict__ Wt_hi, __nv_bfloat16* __restrict__ Wt_lo) {
    constexpr int NPG = 512;
    const int b = blockIdx.x, t = threadIdx.x;
    if (b == BGR) {
#pragma unroll
        for (int it = 0; it < 16; it++) {
            int idx = t + it*1024;
            int n = idx >> 7, k = idx & 127;
            float v = W[k*128 + n];
            __nv_bfloat16 h = __float2bfloat16(v);
            Wt_hi[idx] = h;
            Wt_lo[idx] = __float2bfloat16(v - __bfloat162float(h));
        }
        return;
    }
    __shared__ unsigned short s_src[EPG];
    __shared__ float          s_w  [EPG];
    __shared__ int   s_cnt [NPG];
    __shared__ int   s_cur [NPG];
    __shared__ int   s_offl[NPG];
    __shared__ float s_dinv[NPG];
    __shared__ int   s_ws  [NPG/32];
    const int ebase = b * EPG;
    const int nbase = b * NPG;
    const int lane = t & 31, wid = t >> 5;
    if (t < NPG) s_cnt[t] = 0;
    __syncthreads();

    int ls[4], ldst[4];
#pragma unroll
    for (int u = 0; u < 4; u++) {
        int e = ebase + u*1024 + t;
        int s = esrc[e], d = edst[e];
        ls[u]   = s - nbase;
        ldst[u] = d - nbase;
        atomicAdd(&s_cnt[ldst[u]], 1);
    }
    __syncthreads();

    int c = 0, vincl = 0;
    if (t < NPG) {
        c = s_cnt[t];
        vincl = c;
#pragma unroll
        for (int d = 1; d < 32; d <<= 1) {
            int nv = __shfl_up_sync(0xFFFFFFFFu, vincl, d);
            if (lane >= d) vincl += nv;
        }
        if (lane == 31) s_ws[wid] = vincl;
        cnt_g[nbase + t] = c;
        s_dinv[t] = rsqrtf((float)c + 1.f);
    }
    __syncthreads();
    if (t < 32) {
        constexpr int NW = NPG/32;
        int v = (t < NW) ? s_ws[t] : 0;
#pragma unroll
        for (int d = 1; d < 32; d <<= 1) {
            int nv = __shfl_up_sync(0xFFFFFFFFu, v, d);
            if (lane >= d) v += nv;
        }
        if (t < NW) s_ws[t] = v;
    }
    __syncthreads();
    if (t < NPG) {
        int base = (wid > 0) ? s_ws[wid - 1] : 0;
        int excl = base + vincl - c;
        off_g[nbase + t] = ebase + excl;
        s_offl[t] = excl;
        s_cur[t]  = excl;
    }
    __syncthreads();

#pragma unroll
    for (int u = 0; u < 4; u++) {
        int pos = atomicAdd(&s_cur[ldst[u]], 1);
        float w = s_dinv[ls[u]] * s_dinv[ldst[u]];
        s_src[pos] = (unsigned short)ls[u];
        s_w  [pos] = w;
        csr_src_g[ebase + pos] = nbase + ls[u];
        csr_w_g  [ebase + pos] = w;
    }
    __syncthreads();

    for (int node = wid; node < NPG; node += 32) {
        int cc = s_cnt[node], o = s_offl[node];
        float self = 1.f / ((float)cc + 1.f);
        size_t gi = (size_t)(nbase + node)*128 + lane*4;
        float4 hv = *(const float4*)(X + gi);
        float4 a0 = make_float4(self*hv.x, self*hv.y, self*hv.z, self*hv.w);
        float4 a1 = make_float4(0,0,0,0), a2 = make_float4(0,0,0,0), a3 = make_float4(0,0,0,0);
        int j = 0;
        for (; j + 4 <= cc; j += 4) {
            int   n0 = s_src[o+j],   n1 = s_src[o+j+1];
            int   n2 = s_src[o+j+2], n3 = s_src[o+j+3];
            float w0 = s_w[o+j],   w1 = s_w[o+j+1];
            float w2 = s_w[o+j+2], w3 = s_w[o+j+3];
            float4 h0 = *(const float4*)(X + (size_t)(nbase+n0)*128 + lane*4);
            float4 h1 = *(const float4*)(X + (size_t)(nbase+n1)*128 + lane*4);
            float4 h2 = *(const float4*)(X + (size_t)(nbase+n2)*128 + lane*4);
            float4 h3 = *(const float4*)(X + (size_t)(nbase+n3)*128 + lane*4);
            a0.x += w0*h0.x; a0.y += w0*h0.y; a0.z += w0*h0.z; a0.w += w0*h0.w;
            a1.x += w1*h1.x; a1.y += w1*h1.y; a1.z += w1*h1.z; a1.w += w1*h1.w;
            a2.x += w2*h2.x; a2.y += w2*h2.y; a2.z += w2*h2.z; a2.w += w2*h2.w;
            a3.x += w3*h3.x; a3.y += w3*h3.y; a3.z += w3*h3.z; a3.w += w3*h3.w;
        }
        for (; j < cc; j++) {
            int s = s_src[o+j]; float w = s_w[o+j];
            float4 hs = *(const float4*)(X + (size_t)(nbase+s)*128 + lane*4);
            a0.x += w*hs.x; a0.y += w*hs.y; a0.z += w*hs.z; a0.w += w*hs.w;
        }
        a0.x += a1.x + a2.x + a3.x;
        a0.y += a1.y + a2.y + a3.y;
        a0.z += a1.z + a2.z + a3.z;
        a0.w += a1.w + a2.w + a3.w;
        float f[4] = {a0.x, a0.y, a0.z, a0.w};
        __nv_bfloat16 hi4[4], lo4[4];
#pragma unroll
        for (int e = 0; e < 4; e++) {
            hi4[e] = __float2bfloat16(f[e]);
            lo4[e] = __float2bfloat16(f[e] - __bfloat162float(hi4[e]));
        }
        *(uint2*)(Xa_hi + gi) = *(uint2*)hi4;
        *(uint2*)(Xa_lo + gi) = *(uint2*)lo4;
    }
}

// =====================================================================
// Tensor-core GEMM, 64x128 tile (3 blocks/SM): ldmatrix + mma.sync.
//   H[M,128] = relu(Xa @ W + b); epilogue computes s0 = H.Ws
// =====================================================================
__device__ __forceinline__ void mma_bf16(float* d, const unsigned* a, const unsigned* b) {
    asm volatile(
        "mma.sync.aligned.m16n8k16.row.col.f32.bf16.bf16.f32 "
        "{%0,%1,%2,%3}, {%4,%5,%6,%7}, {%8,%9}, {%0,%1,%2,%3};\n"
        : "+f"(d[0]), "+f"(d[1]), "+f"(d[2]), "+f"(d[3])
        : "r"(a[0]), "r"(a[1]), "r"(a[2]), "r"(a[3]), "r"(b[0]), "r"(b[1]));
}
__device__ __forceinline__ void ldsm4(unsigned* r, uint32_t a) {
    asm volatile("ldmatrix.sync.aligned.m8n8.x4.shared.b16 {%0,%1,%2,%3}, [%4];\n"
        : "=r"(r[0]), "=r"(r[1]), "=r"(r[2]), "=r"(r[3]) : "r"(a));
}

__global__ __launch_bounds__(256, 3)
void k_gemm_tc(const __nv_bfloat16* __restrict__ A_hi,
               const __nv_bfloat16* __restrict__ A_lo,
               const __nv_bfloat16* __restrict__ Wt_hi,
               const __nv_bfloat16* __restrict__ Wt_lo,
               const float* __restrict__ bias, const float* __restrict__ Ws,
               float* __restrict__ C, float* __restrict__ s0) {
    __shared__ __align__(16) __nv_bfloat16 As_hi[64][40];
    __shared__ __align__(16) __nv_bfloat16 As_lo[64][40];
    __shared__ __align__(16) __nv_bfloat16 Bt_hi[128][40];
    __shared__ __align__(16) __nv_bfloat16 Bt_lo[128][40];
    __shared__ float s0part[2][64];

    const int t = threadIdx.x;
    const int warp = t >> 5, lane = t & 31;
    const int warpM = warp >> 1, warpN = warp & 1;   // 4 x 2
    const int row0 = blockIdx.x * 64;
    const int lq = lane >> 2;
    const int lr = lane & 3;

    const uint32_t sAhi = (uint32_t)__cvta_generic_to_shared(&As_hi[0][0]);
    const uint32_t sAlo = (uint32_t)__cvta_generic_to_shared(&As_lo[0][0]);
    const uint32_t sBhi = (uint32_t)__cvta_generic_to_shared(&Bt_hi[0][0]);
    const uint32_t sBlo = (uint32_t)__cvta_generic_to_shared(&Bt_lo[0][0]);

    // ldmatrix per-thread source addresses (byte offsets)
    const int aOff = ((warpM*16 + (lane & 7) + ((lane >> 3) & 1)*8) * 40
                      + (lane >> 4)*8) * 2;
    const int bOff = ((warpN*64 + (lane & 7) + (lane >> 4)*8) * 40
                      + ((lane >> 3) & 1)*8) * 2;

    float acc[8][4];
#pragma unroll
    for (int nt = 0; nt < 8; nt++)
#pragma unroll
        for (int r = 0; r < 4; r++) acc[nt][r] = 0.f;

    for (int kc = 0; kc < 4; kc++) {
        // ---- uint4 smem fill: A (64 rows), B (128 rows) ----
        {
            int row = t >> 2;
            int kq  = (t & 3) * 8;
            size_t ga = (size_t)(row0 + row)*128 + kc*32 + kq;
            *(uint4*)&As_hi[row][kq] = *(const uint4*)(A_hi + ga);
            *(uint4*)&As_lo[row][kq] = *(const uint4*)(A_lo + ga);
        }
#pragma unroll
        for (int it = 0; it < 2; it++) {
            int idx = t + it*256;
            int row = idx >> 2;
            int kq  = (idx & 3) * 8;
            size_t gb = (size_t)row*128 + kc*32 + kq;
            *(uint4*)&Bt_hi[row][kq] = *(const uint4*)(Wt_hi + gb);
            *(uint4*)&Bt_lo[row][kq] = *(const uint4*)(Wt_lo + gb);
        }
        __syncthreads();

#pragma unroll
        for (int ks = 0; ks < 2; ks++) {
            const int kb2 = ks * 32;          // 16 cols * 2 bytes
            unsigned a_hi[4], a_lo[4];
            ldsm4(a_hi, sAhi + aOff + kb2);
            ldsm4(a_lo, sAlo + aOff + kb2);
#pragma unroll
            for (int ntp = 0; ntp < 4; ntp++) {
                unsigned bh[4], bl[4];
                ldsm4(bh, sBhi + bOff + ntp*1280 + kb2);
                ldsm4(bl, sBlo + bOff + ntp*1280 + kb2);
                mma_bf16(acc[2*ntp],   a_hi, bh);
                mma_bf16(acc[2*ntp],   a_lo, bh);
                mma_bf16(acc[2*ntp],   a_hi, bl);
                mma_bf16(acc[2*ntp+1], a_hi, bh + 2);
                mma_bf16(acc[2*ntp+1], a_lo, bh + 2);
                mma_bf16(acc[2*ntp+1], a_hi, bl + 2);
            }
        }
        __syncthreads();
    }

    // ---- epilogue: bias + relu + store + fused s0 = H.Ws ----
    float pacc[2] = {0.f, 0.f};
#pragma unroll
    for (int nt = 0; nt < 8; nt++) {
        int n0 = warpN*64 + nt*8 + 2*lr;
        float bb0 = __ldg(bias + n0), bb1 = __ldg(bias + n0 + 1);
        float ww0 = __ldg(Ws + n0),   ww1 = __ldg(Ws + n0 + 1);
        int r0 = warpM*16 + lq;
        float v0 = fmaxf(acc[nt][0] + bb0, 0.f);
        float v1 = fmaxf(acc[nt][1] + bb1, 0.f);
        float v2 = fmaxf(acc[nt][2] + bb0, 0.f);
        float v3 = fmaxf(acc[nt][3] + bb1, 0.f);
        *(float2*)(C + (size_t)(row0 + r0)*128 + n0)     = make_float2(v0, v1);
        *(float2*)(C + (size_t)(row0 + r0 + 8)*128 + n0) = make_float2(v2, v3);
        pacc[0] += v0*ww0 + v1*ww1;
        pacc[1] += v2*ww0 + v3*ww1;
    }
#pragma unroll
    for (int h = 0; h < 2; h++) {
        float p = pacc[h];
        p += __shfl_xor_sync(0xFFFFFFFFu, p, 1);
        p += __shfl_xor_sync(0xFFFFFFFFu, p, 2);
        if (lr == 0) s0part[warpN][warpM*16 + lq + h*8] = p;
    }
    __syncthreads();
    if (t < 64) s0[row0 + t] = s0part[0][t] + s0part[1][t];
}

// =====================================================================
// k_txr_pa: FUSED stage-s txr with stage-(s+1) prep+agg (per-graph).
// (identical to R15)
// =====================================================================
template<int NPGC, int WRITEBACK, int ACCUM>
__global__ __launch_bounds__(1024)
void k_txr_pa(const int* __restrict__ cntC, const int* __restrict__ offC,
              const int* __restrict__ csr_src, const float* __restrict__ csr_w,
              const float* __restrict__ s0, const float* __restrict__ bs,
              const float* __restrict__ H, float* __restrict__ xnew,
              float* __restrict__ out,
              const int* __restrict__ esrc, const int* __restrict__ edst,
              int* __restrict__ osrc, int* __restrict__ odst,
              int* __restrict__ cntN_g, int* __restrict__ offN_g,
              int* __restrict__ csr_src_g, float* __restrict__ csr_w_g,
              __nv_bfloat16* __restrict__ Xa_hi, __nv_bfloat16* __restrict__ Xa_lo,
              const float* __restrict__ W,
              __nv_bfloat16* __restrict__ Wt_hi, __nv_bfloat16* __restrict__ Wt_lo) {
    constexpr int KC   = NPGC/2;
    constexpr int NPGN = KC;
    const int b = blockIdx.x, t = threadIdx.x;
    if (b == BGR) {
#pragma unroll
        for (int it = 0; it < 16; it++) {
            int idx = t + it*1024;
            int n = idx >> 7, k = idx & 127;
            float v = W[k*128 + n];
            __nv_bfloat16 h = __float2bfloat16(v);
            Wt_hi[idx] = h;
            Wt_lo[idx] = __float2bfloat16(v - __bfloat162float(h));
        }
        return;
    }
    __shared__ union ShU {
        struct {
            unsigned long long keys[NPGC];
            float s0l[NPGC], sc[NPGC], part[NPGC];
            float rmx[2*NPGC], rsm[2*NPGC];
        } x;
        struct {
            unsigned short src[EPG];
            float w[EPG];
            int cnt[NPGN], cur[NPGN], offl[NPGN];
            float dinv[NPGN];
            int ws[NPGN/32];
        } p;
    } sh;
    __shared__ int   s_old[KC];
    __shared__ float s_t  [KC];
    __shared__ int   s_new[NPGC];
    const int nbaseC = b*NPGC, nbaseN = b*NPGN, ebase = b*EPG;
    const int lane = t & 31, wid = t >> 5;
    const bool act  = (t < 2*NPGC);
    const bool lowH = (t < NPGC);

    if (lowH) sh.x.s0l[t] = s0[nbaseC + t];
    __syncthreads();

    int c = 0;
    float accg = 0.f;
    if (act) {
        const int node = lowH ? t : t - NPGC;
        c = cntC[nbaseC + node];
        int o = offC[nbaseC + node];
        int half = c >> 1;
        int jb = lowH ? 0 : half;
        int je = lowH ? half : c;
        float a1 = 0.f, a2 = 0.f, a3 = 0.f;
        int j = jb;
        for (; j + 4 <= je; j += 4) {
            int   n0 = csr_src[o+j] - nbaseC,   n1 = csr_src[o+j+1] - nbaseC;
            int   n2 = csr_src[o+j+2] - nbaseC, n3 = csr_src[o+j+3] - nbaseC;
            float w0 = csr_w[o+j],   w1 = csr_w[o+j+1];
            float w2 = csr_w[o+j+2], w3 = csr_w[o+j+3];
            accg += w0 * sh.x.s0l[n0];
            a1   += w1 * sh.x.s0l[n1];
            a2   += w2 * sh.x.s0l[n2];
            a3   += w3 * sh.x.s0l[n3];
        }
        for (; j < je; j++) accg += csr_w[o+j] * sh.x.s0l[csr_src[o+j] - nbaseC];
        accg += a1 + a2 + a3;
        if (!lowH) sh.x.part[node] = accg;
    }
    __syncthreads();
    if (lowH) {
        float total = bs[0] + sh.x.s0l[t] / ((float)c + 1.f) + accg + sh.x.part[t];
        sh.x.sc[t] = total;
        unsigned u  = __float_as_uint(total);
        unsigned ou = u ^ ((u & 0x80000000u) ? 0xFFFFFFFFu : 0x80000000u);
        sh.x.keys[t] = ((unsigned long long)(~ou) << 32) | (unsigned)t;
    }
    __syncthreads();

    for (int kk = 2; kk <= NPGC; kk <<= 1) {
        for (int js = kk >> 1; js >= 32; js >>= 1) {
            if (lowH) {
                int ixj = t ^ js;
                if (ixj > t) {
                    bool up = ((t & kk) == 0);
                    unsigned long long a = sh.x.keys[t], cc2 = sh.x.keys[ixj];
                    if ((a > cc2) == up) { sh.x.keys[t] = cc2; sh.x.keys[ixj] = a; }
                }
            }
            __syncthreads();
        }
        if (lowH) {
            unsigned long long v = sh.x.keys[t];
            const bool up = ((t & kk) == 0);
            int js0 = (kk >> 1) < 16 ? (kk >> 1) : 16;
            for (int js = js0; js > 0; js >>= 1) {
                unsigned long long p = __shfl_xor_sync(0xFFFFFFFFu, v, js);
                bool keepSmall = (((t & js) == 0) == up);
                if ((p < v) == keepSmall) v = p;
            }
            sh.x.keys[t] = v;
        }
        __syncthreads();
    }

    if (lowH) {
        int idx = (int)(sh.x.keys[t] & 0xFFFFFFFFull);
        if (t < KC) {
            s_old[t] = idx;
            s_t[t]   = tanhf(sh.x.sc[idx]);
            s_new[idx] = b*KC + t;
        } else {
            s_new[idx] = -1;
        }
    }
    __syncthreads();

    {
        constexpr int G = (2*NPGC)/128;
        const int col = t & 127, g = t >> 7;
        float mx = -3.402823466e38f, sm = 0.f;
        if (act) {
            for (int jr = g; jr < KC; jr += G) {
                float v = H[(size_t)(nbaseC + s_old[jr])*128 + col] * s_t[jr];
                xnew[(size_t)(b*KC + jr)*128 + col] = v;
                mx = fmaxf(mx, v); sm += v;
            }
            sh.x.rmx[g*128 + col] = mx;
            sh.x.rsm[g*128 + col] = sm;
        }
        __syncthreads();
        if (act && g == 0) {
#pragma unroll
            for (int gg = 1; gg < G; gg++) {
                mx = fmaxf(mx, sh.x.rmx[gg*128 + col]);
                sm += sh.x.rsm[gg*128 + col];
            }
            if (ACCUM) {
                out[b*256 + col]       += mx;
                out[b*256 + 128 + col] += sm / (float)KC;
            } else {
                out[b*256 + col]       = mx;
                out[b*256 + 128 + col] = sm / (float)KC;
            }
        }
    }
    __syncthreads();

    if (t < NPGN) sh.p.cnt[t] = 0;
    __syncthreads();

    int ls[4], ldst[4];
#pragma unroll
    for (int u = 0; u < 4; u++) {
        int e = ebase + u*1024 + t;
        int s = esrc[e], d = edst[e];
        if (d >= 0) {
            int ns = s_new[s - nbaseC], nd = s_new[d - nbaseC];
            if (ns < 0 || nd < 0) d = -1;
            else { s = ns; d = nd; }
        }
        if (WRITEBACK) { osrc[e] = s; odst[e] = d; }
        if (d >= 0) {
            ls[u]   = s - nbaseN;
            ldst[u] = d - nbaseN;
            atomicAdd(&sh.p.cnt[ldst[u]], 1);
        } else ldst[u] = -1;
    }
    __syncthreads();

    int cc = 0, vincl = 0;
    if (t < NPGN) {
        cc = sh.p.cnt[t];
        vincl = cc;
#pragma unroll
        for (int d = 1; d < 32; d <<= 1) {
            int nv = __shfl_up_sync(0xFFFFFFFFu, vincl, d);
            if (lane >= d) vincl += nv;
        }
        if (lane == 31) sh.p.ws[wid] = vincl;
        cntN_g[nbaseN + t] = cc;
        sh.p.dinv[t] = rsqrtf((float)cc + 1.f);
    }
    __syncthreads();
    if (t < 32) {
        constexpr int NW = NPGN/32;
        int v = (t < NW) ? sh.p.ws[t] : 0;
#pragma unroll
        for (int d = 1; d < 32; d <<= 1) {
            int nv = __shfl_up_sync(0xFFFFFFFFu, v, d);
            if (lane >= d) v += nv;
        }
        if (t < NW) sh.p.ws[t] = v;
    }
    __syncthreads();
    if (t < NPGN) {
        int base = (wid > 0) ? sh.p.ws[wid - 1] : 0;
        int excl = base + vincl - cc;
        offN_g[nbaseN + t] = ebase + excl;
        sh.p.offl[t] = excl;
        sh.p.cur[t]  = excl;
    }
    __syncthreads();

#pragma unroll
    for (int u = 0; u < 4; u++) {
        if (ldst[u] >= 0) {
            int pos = atomicAdd(&sh.p.cur[ldst[u]], 1);
            float w = sh.p.dinv[ls[u]] * sh.p.dinv[ldst[u]];
            sh.p.src[pos] = (unsigned short)ls[u];
            sh.p.w  [pos] = w;
            csr_src_g[ebase + pos] = nbaseN + ls[u];
            csr_w_g  [ebase + pos] = w;
        }
    }
    __syncthreads();

    for (int node = wid; node < NPGN; node += 32) {
        int cn = sh.p.cnt[node], o = sh.p.offl[node];
        float self = 1.f / ((float)cn + 1.f);
        size_t gi = (size_t)(nbaseN + node)*128 + lane*4;
        float4 hv = *(const float4*)(xnew + gi);
        float4 a0 = make_float4(self*hv.x, self*hv.y, self*hv.z, self*hv.w);
        float4 a1 = make_float4(0,0,0,0), a2 = make_float4(0,0,0,0), a3 = make_float4(0,0,0,0);
        int j = 0;
        for (; j + 4 <= cn; j += 4) {
            int   n0 = sh.p.src[o+j],   n1 = sh.p.src[o+j+1];
            int   n2 = sh.p.src[o+j+2], n3 = sh.p.src[o+j+3];
            float w0 = sh.p.w[o+j],   w1 = sh.p.w[o+j+1];
            float w2 = sh.p.w[o+j+2], w3 = sh.p.w[o+j+3];
            float4 h0 = *(const float4*)(xnew + (size_t)(nbaseN+n0)*128 + lane*4);
            float4 h1 = *(const float4*)(xnew + (size_t)(nbaseN+n1)*128 + lane*4);
            float4 h2 = *(const float4*)(xnew + (size_t)(nbaseN+n2)*128 + lane*4);
            float4 h3 = *(const float4*)(xnew + (size_t)(nbaseN+n3)*128 + lane*4);
            a0.x += w0*h0.x; a0.y += w0*h0.y; a0.z += w0*h0.z; a0.w += w0*h0.w;
            a1.x += w1*h1.x; a1.y += w1*h1.y; a1.z += w1*h1.z; a1.w += w1*h1.w;
            a2.x += w2*h2.x; a2.y += w2*h2.y; a2.z += w2*h2.z; a2.w += w2*h2.w;
            a3.x += w3*h3.x; a3.y += w3*h3.y; a3.z += w3*h3.z; a3.w += w3*h3.w;
        }
        for (; j < cn; j++) {
            int s = sh.p.src[o+j]; float w = sh.p.w[o+j];
            float4 hs = *(const float4*)(xnew + (size_t)(nbaseN+s)*128 + lane*4);
            a0.x += w*hs.x; a0.y += w*hs.y; a0.z += w*hs.z; a0.w += w*hs.w;
        }
        a0.x += a1.x + a2.x + a3.x;
        a0.y += a1.y + a2.y + a3.y;
        a0.z += a1.z + a2.z + a3.z;
        a0.w += a1.w + a2.w + a3.w;
        float f[4] = {a0.x, a0.y, a0.z, a0.w};
        __nv_bfloat16 hi4[4], lo4[4];
#pragma unroll
        for (int e = 0; e < 4; e++) {
            hi4[e] = __float2bfloat16(f[e]);
            lo4[e] = __float2bfloat16(f[e] - __bfloat162float(hi4[e]));
        }
        *(uint2*)(Xa_hi + gi) = *(uint2*)hi4;
        *(uint2*)(Xa_lo + gi) = *(uint2*)lo4;
    }
}

// =====================================================================
// k_txr: final standalone txr (stage 3) — 2*NPG threads (identical R15)
// =====================================================================
template<int NPG, int ACCUM>
__global__ void k_txr(const int* __restrict__ cnt, const int* __restrict__ off,
                      const int* __restrict__ csr_src,
                      const float* __restrict__ csr_w,
                      const float* __restrict__ s0, const float* __restrict__ bs,
                      const float* __restrict__ H, float* __restrict__ xnew,
                      float* __restrict__ out) {
    constexpr int K  = NPG/2;
    constexpr int T2 = 2*NPG;
    constexpr int G  = T2/128;
    __shared__ unsigned long long keys[NPG];
    __shared__ float s_s0l [NPG];
    __shared__ float s_sc  [NPG];
    __shared__ float s_part[NPG];
    __shared__ int   s_old [K];
    __shared__ float s_t   [K];
    __shared__ float r_mx  [T2];
    __shared__ float r_sm  [T2];
    const int b = blockIdx.x, t = threadIdx.x;
    const int nbase = b*NPG;
    const bool lowH = (t < NPG);
    const int node = lowH ? t : t - NPG;

    if (lowH) s_s0l[t] = s0[nbase + t];
    __syncthreads();

    int c = cnt[nbase + node], o = off[nbase + node];
    int half = c >> 1;
    int jb = lowH ? 0 : half;
    int je = lowH ? half : c;
    float acc = 0.f, acc1 = 0.f, acc2 = 0.f, acc3 = 0.f;
    int j = jb;
    for (; j + 4 <= je; j += 4) {
        int   n0 = csr_src[o+j] - nbase,   n1 = csr_src[o+j+1] - nbase;
        int   n2 = csr_src[o+j+2] - nbase, n3 = csr_src[o+j+3] - nbase;
        float w0 = csr_w[o+j],   w1 = csr_w[o+j+1];
        float w2 = csr_w[o+j+2], w3 = csr_w[o+j+3];
        acc  += w0 * s_s0l[n0];
        acc1 += w1 * s_s0l[n1];
        acc2 += w2 * s_s0l[n2];
        acc3 += w3 * s_s0l[n3];
    }
    for (; j < je; j++) acc += csr_w[o+j] * s_s0l[csr_src[o+j] - nbase];
    acc += acc1 + acc2 + acc3;
    if (!lowH) s_part[node] = acc;
    __syncthreads();
    if (lowH) {
        float total = bs[0] + s_s0l[t] / ((float)c + 1.f) + acc + s_part[t];
        s_sc[t] = total;
        unsigned u  = __float_as_uint(total);
        unsigned ou = u ^ ((u & 0x80000000u) ? 0xFFFFFFFFu : 0x80000000u);
        keys[t] = ((unsigned long long)(~ou) << 32) | (unsigned)t;
    }
    __syncthreads();

    for (int kk = 2; kk <= NPG; kk <<= 1) {
        for (int js = kk >> 1; js >= 32; js >>= 1) {
            if (lowH) {
                int ixj = t ^ js;
                if (ixj > t) {
                    bool up = ((t & kk) == 0);
                    unsigned long long a = keys[t], cc2 = keys[ixj];
                    if ((a > cc2) == up) { keys[t] = cc2; keys[ixj] = a; }
                }
            }
            __syncthreads();
        }
        if (lowH) {
            unsigned long long v = keys[t];
            const bool up = ((t & kk) == 0);
            int js0 = (kk >> 1) < 16 ? (kk >> 1) : 16;
            for (int js = js0; js > 0; js >>= 1) {
                unsigned long long p = __shfl_xor_sync(0xFFFFFFFFu, v, js);
                bool keepSmall = (((t & js) == 0) == up);
                if ((p < v) == keepSmall) v = p;
            }
            keys[t] = v;
        }
        __syncthreads();
    }

    if (lowH && t < K) {
        int idx = (int)(keys[t] & 0xFFFFFFFFull);
        s_old[t] = idx;
        s_t[t]   = tanhf(s_sc[idx]);
    }
    __syncthreads();

    const int col = t & 127, g = t >> 7;
    float mx = -3.402823466e38f, sm = 0.f;
    for (int jr = g; jr < K; jr += G) {
        float v = H[(size_t)(nbase + s_old[jr])*128 + col] * s_t[jr];
        xnew[(size_t)(b*K + jr)*128 + col] = v;
        mx = fmaxf(mx, v); sm += v;
    }
    r_mx[g*128 + col] = mx;
    r_sm[g*128 + col] = sm;
    __syncthreads();
    if (g == 0) {
#pragma unroll
        for (int gg = 1; gg < G; gg++) {
            mx = fmaxf(mx, r_mx[gg*128 + col]);
            sm += r_sm[gg*128 + col];
        }
        if (ACCUM) {
            out[b*256 + col]       += mx;
            out[b*256 + 128 + col] += sm / (float)K;
        } else {
            out[b*256 + col]       = mx;
            out[b*256 + 128 + col] = sm / (float)K;
        }
    }
}

// =====================================================================
extern "C" void kernel_launch(void* const* d_in, const int* in_sizes, int n_in,
                              void* d_out, int out_size) {
    const float* x   = (const float*)d_in[0];
    const int*   ei  = (const int*)  d_in[1];
    const float* W1  = (const float*)d_in[3];
    const float* b1  = (const float*)d_in[4];
    const float* Ws1 = (const float*)d_in[5];
    const float* bs1 = (const float*)d_in[6];
    const float* W2  = (const float*)d_in[7];
    const float* b2  = (const float*)d_in[8];
    const float* Ws2 = (const float*)d_in[9];
    const float* bs2 = (const float*)d_in[10];
    const float* W3  = (const float*)d_in[11];
    const float* b3  = (const float*)d_in[12];
    const float* Ws3 = (const float*)d_in[13];
    const float* bs3 = (const float*)d_in[14];
    float* out = (float*)d_out;

    __nv_bfloat16 *xah, *xal, *wth, *wtl;
    float *bufB, *bufC, *s0p, *csrw;
    int *srcp, *dstp, *csrs, *cntA, *offA, *cntB, *offB;
    cudaGetSymbolAddress((void**)&xah,  g_Xa_hi);
    cudaGetSymbolAddress((void**)&xal,  g_Xa_lo);
    cudaGetSymbolAddress((void**)&wth,  g_Wt_hi);
    cudaGetSymbolAddress((void**)&wtl,  g_Wt_lo);
    cudaGetSymbolAddress((void**)&bufB, g_bufB);
    cudaGetSymbolAddress((void**)&bufC, g_bufC);
    cudaGetSymbolAddress((void**)&s0p,  g_s0);
    cudaGetSymbolAddress((void**)&csrw, g_csr_w);
    cudaGetSymbolAddress((void**)&srcp, g_src);
    cudaGetSymbolAddress((void**)&dstp, g_dst);
    cudaGetSymbolAddress((void**)&csrs, g_csr_src);
    cudaGetSymbolAddress((void**)&cntA, g_cntA);
    cudaGetSymbolAddress((void**)&offA, g_offA);
    cudaGetSymbolAddress((void**)&cntB, g_cntB);
    cudaGetSymbolAddress((void**)&offB, g_offB);

    const int* ei_src = ei;
    const int* ei_dst = ei + ETOT;

    k_pa1<<<BGR+1,1024>>>(ei_src, ei_dst, cntA, offA, csrs, csrw,
                          x, xah, xal, W1, wth, wtl);
    k_gemm_tc<<<BGR*512/64,256>>>(xah, xal, wth, wtl, b1, Ws1, bufB, s0p);
    k_txr_pa<512,1,0><<<BGR+1,1024>>>(cntA, offA, csrs, csrw, s0p, bs1,
                                      bufB, bufC, out,
                                      ei_src, ei_dst, srcp, dstp,
                                      cntB, offB, csrs, csrw,
                                      xah, xal, W2, wth, wtl);
    k_gemm_tc<<<BGR*256/64,256>>>(xah, xal, wth, wtl, b2, Ws2, bufB, s0p);
    k_txr_pa<256,0,1><<<BGR+1,1024>>>(cntB, offB, csrs, csrw, s0p, bs2,
                                      bufB, bufC, out,
                                      srcp, dstp, srcp, dstp,
                                      cntA, offA, csrs, csrw,
                                      xah, xal, W3, wth, wtl);
    k_gemm_tc<<<BGR*128/64,256>>>(xah, xal, wth, wtl, b3, Ws3, bufB, s0p);
    k_txr<128,1><<<BGR,256>>>(cntA, offA, csrs, csrw, s0p, bs3,
                              bufB, bufC, out);
}